// round 16
// baseline (speedup 1.0000x reference)
#include <cuda_runtime.h>
#include <cstdint>

#define BB 4
#define AA 9
#define HH 50
#define WW 76
#define NN (AA * HH * WW)          // 34200 boxes per image
#define PRE 4000
#define POST 300
#define SORTN 4096                 // slow path sort size
#define FASTN 2048                 // fast path max sort size
#define RANKT 896u                 // coarse threshold target rank (=> cnt >= 896 > NC)
#define NC 512                     // matrix-NMS candidate prefix
#define NMS_THR 0.7f
#define NBINS 2048
#define CHUNK 1088                 // per-warp compaction chunk (34*32)

// ---------------- static scratch ----------------
__device__ float4   d_props[BB * NN];
__device__ unsigned d_keys [BB * NN];
__device__ unsigned d_hist [BB * NBINS];   // zero at load; fused_kernel re-zeroes each run

// ---------------- helpers ----------------
__device__ __forceinline__ float areaf(float4 b) {
    return __fmul_rn(__fsub_rn(b.z, b.x), __fsub_rn(b.w, b.y));
}

// Decision-exact IoU > 0.7 with banded compare: FDIV only inside [0.67, 0.73] band.
__device__ __forceinline__ bool iou_gt(float4 a, float aA, float4 b, float aB) {
    float xx1 = fmaxf(a.x, b.x);
    float yy1 = fmaxf(a.y, b.y);
    float xx2 = fminf(a.z, b.z);
    float yy2 = fminf(a.w, b.w);
    float w = fmaxf(__fsub_rn(xx2, xx1), 0.0f);
    float h = fmaxf(__fsub_rn(yy2, yy1), 0.0f);
    float inter = __fmul_rn(w, h);
    float denom = __fadd_rn(__fsub_rn(__fadd_rn(aA, aB), inter), 1e-9f);
    if (inter < __fmul_rn(0.67f, denom)) return false;
    if (inter > __fmul_rn(0.73f, denom)) return true;
    return __fdiv_rn(inter, denom) > NMS_THR;
}

// ---------------- 1) decode + key + shared-agg histogram + prefill ----------------
__global__ void decode_kernel(const float* __restrict__ scores,
                              const float* __restrict__ deltas,
                              const float* __restrict__ im_info,
                              const float* __restrict__ anchors,
                              float* __restrict__ out) {
    __shared__ unsigned shist[NBINS];
    const int tid = threadIdx.x;
    const int b = blockIdx.y;
    const int i = blockIdx.x * 256 + tid;

    #pragma unroll
    for (int r = 0; r < NBINS / 256; r++) shist[tid + r * 256] = 0;

    int g = (b * gridDim.x + blockIdx.x) * 256 + tid;
    if (g < BB * POST * 5) {
        int col = g % 5;
        int bb = g / (POST * 5);
        out[g] = (col == 0) ? (float)bb : 0.0f;
    }
    __syncthreads();

    if (i < NN) {
        int a = i % AA;
        int p = i / AA;
        int x = p % WW;
        int y = p / WW;

        float sx = (float)(x * 16);
        float sy = (float)(y * 16);
        float ax1 = __fadd_rn(anchors[a * 4 + 0], sx);
        float ay1 = __fadd_rn(anchors[a * 4 + 1], sy);
        float ax2 = __fadd_rn(anchors[a * 4 + 2], sx);
        float ay2 = __fadd_rn(anchors[a * 4 + 3], sy);

        float w  = __fadd_rn(__fsub_rn(ax2, ax1), 1.0f);
        float h  = __fadd_rn(__fsub_rn(ay2, ay1), 1.0f);
        float cx = __fadd_rn(ax1, __fmul_rn(0.5f, w));
        float cy = __fadd_rn(ay1, __fmul_rn(0.5f, h));

        const int HW = HH * WW;
        size_t dbase = ((size_t)b * 4 * AA + a * 4) * HW + (size_t)y * WW + x;
        float dx  = deltas[dbase];
        float dy  = deltas[dbase + HW];
        float dz  = deltas[dbase + 2 * HW];
        float dw_ = deltas[dbase + 3 * HW];

        float pcx = __fadd_rn(__fmul_rn(dx, w), cx);
        float pcy = __fadd_rn(__fmul_rn(dy, h), cy);
        float pw  = __fmul_rn(expf(dz),  w);
        float ph  = __fmul_rn(expf(dw_), h);

        float x1 = __fsub_rn(pcx, __fmul_rn(0.5f, pw));
        float y1 = __fsub_rn(pcy, __fmul_rn(0.5f, ph));
        float x2 = __fadd_rn(pcx, __fmul_rn(0.5f, pw));
        float y2 = __fadd_rn(pcy, __fmul_rn(0.5f, ph));

        float hiw = __fsub_rn(im_info[b * 3 + 1], 1.0f);
        float hih = __fsub_rn(im_info[b * 3 + 0], 1.0f);
        x1 = fminf(fmaxf(x1, 0.0f), hiw);
        y1 = fminf(fmaxf(y1, 0.0f), hih);
        x2 = fminf(fmaxf(x2, 0.0f), hiw);
        y2 = fminf(fmaxf(y2, 0.0f), hih);

        int t = b * NN + i;
        d_props[t] = make_float4(x1, y1, x2, y2);

        float s = scores[((size_t)b * AA + a) * HW + (size_t)y * WW + x];
        unsigned bits = __float_as_uint(s);
        unsigned key = (bits & 0x80000000u) ? ~bits : (bits | 0x80000000u);
        d_keys[t] = key;
        atomicAdd(&shist[key >> 21], 1u);
    }
    __syncthreads();
    #pragma unroll
    for (int r = 0; r < NBINS / 256; r++) {
        int bin = tid + r * 256;
        unsigned c = shist[bin];
        if (c) atomicAdd(&d_hist[b * NBINS + bin], c);
    }
}

// ---------------- shared-mem state ----------------
struct FastState {
    float4 cbox[NC];
    float  carea[NC];
    int    klist[POST];
};
struct NmsSlow {
    float4 kbox[POST];
    float  karea[POST];
    float4 cbox[64];
    float  carea[64];
    int    flags[64];
};
union SharedU {
    unsigned  hist[NBINS];
    FastState f;
    NmsSlow   s;
};

// ---------------- 2) FUSED: select + sort + matrix NMS (+ slow fallback) ----------------
__global__ void __launch_bounds__(1024) fused_kernel(float* __restrict__ out) {
    const int img = blockIdx.x;
    const unsigned* keys = d_keys + (size_t)img * NN;
    const float4* props = d_props + (size_t)img * NN;
    const int tid = threadIdx.x;
    const int lane = tid & 31, wid = tid >> 5;

    __shared__ __align__(16) unsigned long long sh_sort[SORTN];   // sort buffer / 512x512 bit matrix / slow sort
    __shared__ SharedU u;
    __shared__ unsigned csum[64];
    __shared__ unsigned warpsum[32];
    __shared__ unsigned cursor, sh_cnt, sh_T, sh_need, sh_bucket, eqbase, chunk_total;
    __shared__ int kept_sh;

    // ---- read precomputed histogram, zero it for next replay ----
    unsigned* ghist = d_hist + img * NBINS;
    #pragma unroll
    for (int rep = 0; rep < NBINS / 1024; rep++) {
        int i = tid + rep * 1024;
        u.hist[i] = ghist[i];
        ghist[i] = 0;
    }
    __syncthreads();
    if (tid < 64) {
        unsigned s = 0;
        #pragma unroll
        for (int v = 0; v < 32; v++) s += u.hist[tid * 32 + v];
        csum[tid] = s;
    }
    __syncthreads();
    if (tid == 0) {
        unsigned cum = 0;
        int ch = 63;
        for (; ch > 0; ch--) {
            if (cum + csum[ch] >= RANKT) break;
            cum += csum[ch];
        }
        int bsel = ch * 32;
        for (int v = ch * 32 + 31; v >= ch * 32; v--) {
            if (cum + u.hist[v] >= RANKT) { bsel = v; break; }
            cum += u.hist[v];
        }
        sh_T = (unsigned)bsel << 21;
        sh_cnt = cum + u.hist[bsel];
        cursor = 0;
        kept_sh = 0;
    }
    __syncthreads();
    const unsigned T = sh_T;
    const int cnt = (int)sh_cnt;          // >= RANKT = 896 > NC always
    const bool fastok = (cnt <= FASTN);
    int kept = 0;

    if (fastok) {
        const int sortn = (cnt <= 1024) ? 1024 : 2048;
        const int reps  = sortn >> 10;    // 1 or 2

        // ---- atomic-free two-pass compaction (per-warp chunks, warp-uniform loops) ----
        sh_sort[tid] = 0xFFFFFFFFFFFFFFFFull;
        if (reps == 2) sh_sort[tid + 1024] = 0xFFFFFFFFFFFFFFFFull;

        const int lo = wid * CHUNK;
        const int hi = min(lo + CHUNK, NN);
        const int iters = (hi - lo + 31) >> 5;   // warp-uniform

        unsigned mycnt = 0;
        for (int it = 0; it < iters; it++) {
            int i = lo + it * 32 + lane;
            bool take = (i < hi) && (keys[i] >= T);
            unsigned m = __ballot_sync(0xffffffffu, take);
            mycnt += (unsigned)__popc(m);
        }
        if (lane == 0) warpsum[wid] = mycnt;
        __syncthreads();
        if (wid == 0) {
            unsigned wv = warpsum[lane];
            unsigned vv = wv;
            #pragma unroll
            for (int off = 1; off < 32; off <<= 1) {
                unsigned tmp = __shfl_up_sync(0xffffffffu, vv, off);
                if (lane >= off) vv += tmp;
            }
            warpsum[lane] = vv - wv;
        }
        __syncthreads();
        unsigned basew = warpsum[wid];
        for (int it = 0; it < iters; it++) {
            int i = lo + it * 32 + lane;
            unsigned k = (i < hi) ? keys[i] : 0u;
            bool take = (i < hi) && (k >= T);
            unsigned m = __ballot_sync(0xffffffffu, take);
            if (take) {
                unsigned pos = basew + (unsigned)__popc(m & ((1u << lane) - 1u));
                sh_sort[pos] = (((unsigned long long)(~k)) << 32) | (unsigned)i;
            }
            basew += (unsigned)__popc(m);
        }
        __syncthreads();

        // ---- adaptive bitonic sort ascending on (~key, idx): key desc, idx asc ----
        unsigned prev_stride = 0xFFFFu;
        for (unsigned size = 2; size <= (unsigned)sortn; size <<= 1) {
            for (unsigned stride = size >> 1; stride > 0; stride >>= 1) {
                if (stride >= 32 || prev_stride >= 32) __syncthreads();
                else __syncwarp();
                for (int rep = 0; rep < reps; rep++) {
                    int t = tid + rep * 1024;
                    int l = t ^ (int)stride;
                    if (l > t) {
                        unsigned long long a = sh_sort[t], b = sh_sort[l];
                        bool asc = ((t & (int)size) == 0);
                        if ((a > b) == asc) { sh_sort[t] = b; sh_sort[l] = a; }
                    }
                }
                prev_stride = stride;
            }
        }
        __syncthreads();

        // ---- load top-512 candidate boxes into shared ----
        if (tid < NC) {
            unsigned idx = (unsigned)(sh_sort[tid] & 0xFFFFFFFFull);
            float4 bx = props[idx];
            u.f.cbox[tid]  = bx;
            u.f.carea[tid] = areaf(bx);
        }
        __syncthreads();   // all sh_sort reads done; matrix may overwrite

        // ---- 512x512 suppression bit matrix (overlays sh_sort; 32 KB) ----
        unsigned* mat = (unsigned*)sh_sort;   // mat[r*16 + w]
        #pragma unroll
        for (int rep = 0; rep < 8; rep++)
            mat[tid + rep * 1024] = 0u;
        __syncthreads();

        // distance-folded upper-triangle enumeration: 2 threads/row, 128 distances each
        {
            const int r = tid >> 1;
            const int dbase = 1 + (tid & 1) * 128;
            float4 rb = u.f.cbox[r];
            float  ra = u.f.carea[r];
            for (int j = 0; j < 128; j++) {
                int c0 = r + dbase + j;
                int c = (c0 >= NC) ? c0 - NC : c0;
                float4 cb = u.f.cbox[c];
                float  ca = u.f.carea[c];
                if (iou_gt(rb, ra, cb, ca)) {
                    int a = min(r, c), b = max(r, c);
                    atomicOr(&mat[a * 16 + (b >> 5)], 1u << (b & 31));
                }
            }
        }
        __syncthreads();

        // ---- serial greedy bit-walk (thread 0) ----
        if (tid == 0) {
            unsigned long long rem[8];
            #pragma unroll
            for (int w = 0; w < 8; w++) rem[w] = 0xFFFFFFFFFFFFFFFFull;
            int kl = 0;
            for (int w = 0; w < 8 && kl < POST; w++) {
                while (rem[w] && kl < POST) {
                    int cb = __ffsll((long long)rem[w]) - 1;
                    int c = w * 64 + cb;
                    u.f.klist[kl++] = c;
                    const uint4* mr = (const uint4*)&mat[c * 16];
                    uint4 m0 = mr[0], m1 = mr[1], m2 = mr[2], m3 = mr[3];
                    rem[0] &= ~(((unsigned long long)m0.y << 32) | m0.x);
                    rem[1] &= ~(((unsigned long long)m0.w << 32) | m0.z);
                    rem[2] &= ~(((unsigned long long)m1.y << 32) | m1.x);
                    rem[3] &= ~(((unsigned long long)m1.w << 32) | m1.z);
                    rem[4] &= ~(((unsigned long long)m2.y << 32) | m2.x);
                    rem[5] &= ~(((unsigned long long)m2.w << 32) | m2.z);
                    rem[6] &= ~(((unsigned long long)m3.y << 32) | m3.x);
                    rem[7] &= ~(((unsigned long long)m3.w << 32) | m3.z);
                    rem[w] &= ~(1ull << cb);
                }
            }
            kept_sh = kl;
        }
        __syncthreads();
        kept = kept_sh;

        if (kept >= POST) {
            if (tid < POST) {
                float4 cc = u.f.cbox[u.f.klist[tid]];
                float* o = out + ((size_t)img * POST + tid) * 5;
                o[1] = cc.x; o[2] = cc.y; o[3] = cc.z; o[4] = cc.w;
            }
            return;
        }
        // consumed all 512 without 300 keeps (cnt > 512 always) -> slow fallback
    }

    // ================= SLOW fallback (exact top-4000 pipeline) =================
    if (tid == 0) sh_need = PRE;
    __syncthreads();

    unsigned prefix = 0, pmask = 0;
    const int shifts[3]  = {21, 10, 0};
    const int nbins3[3]  = {2048, 2048, 1024};
    for (int r = 0; r < 3; r++) {
        const int shift = shifts[r];
        const unsigned bmask = (unsigned)nbins3[r] - 1u;
        for (int i = tid; i < 2048; i += 1024) u.hist[i] = 0;
        __syncthreads();
        for (int i = tid; i < NN; i += 1024) {
            unsigned k = keys[i];
            if ((k & pmask) == prefix) atomicAdd(&u.hist[(k >> shift) & bmask], 1u);
        }
        __syncthreads();
        const int nch = nbins3[r] >> 5;
        if (tid < nch) {
            unsigned s = 0;
            for (int v = 0; v < 32; v++) s += u.hist[tid * 32 + v];
            csum[tid] = s;
        }
        __syncthreads();
        if (tid == 0) {
            unsigned nd = sh_need, cum = 0;
            int ch = nch - 1;
            for (; ch > 0; ch--) {
                if (cum + csum[ch] >= nd) break;
                cum += csum[ch];
            }
            int bsel = ch * 32;
            for (int v = ch * 32 + 31; v >= ch * 32; v--) {
                if (cum + u.hist[v] >= nd) { bsel = v; break; }
                cum += u.hist[v];
            }
            sh_bucket = (unsigned)bsel;
            sh_need = nd - cum;
        }
        __syncthreads();
        prefix |= (sh_bucket << shift);
        pmask  |= (bmask << shift);
        __syncthreads();
    }
    const unsigned Ts = prefix;
    const unsigned need_eq = sh_need;

    if (tid == 0) { cursor = 0; eqbase = 0; }
    for (int i = tid; i < SORTN; i += 1024)
        sh_sort[i] = 0xFFFFFFFFFFFFFFFFull;
    __syncthreads();

    for (int base = 0; base < NN; base += 1024) {
        int i = base + tid;
        unsigned k = (i < NN) ? keys[i] : 0u;
        unsigned isgt = (i < NN && k > Ts) ? 1u : 0u;
        unsigned iseq = (i < NN && k == Ts) ? 1u : 0u;

        unsigned v = iseq;
        #pragma unroll
        for (int off = 1; off < 32; off <<= 1) {
            unsigned tmp = __shfl_up_sync(0xffffffffu, v, off);
            if (lane >= off) v += tmp;
        }
        if (lane == 31) warpsum[wid] = v;
        __syncthreads();
        if (wid == 0) {
            unsigned wv = warpsum[lane];
            unsigned vv = wv;
            #pragma unroll
            for (int off = 1; off < 32; off <<= 1) {
                unsigned tmp = __shfl_up_sync(0xffffffffu, vv, off);
                if (lane >= off) vv += tmp;
            }
            warpsum[lane] = vv - wv;
            if (lane == 31) chunk_total = vv;
        }
        __syncthreads();
        unsigned excl = v - iseq + warpsum[wid];
        unsigned eqrank = eqbase + excl;
        bool take = isgt || (iseq && eqrank < need_eq);
        if (take) {
            unsigned pos = atomicAdd(&cursor, 1u);
            sh_sort[pos] = (((unsigned long long)(~k)) << 32) | (unsigned)i;
        }
        __syncthreads();
        if (tid == 0) eqbase += chunk_total;
        __syncthreads();
    }

    unsigned prev_stride = 0xFFFFu;
    for (unsigned size = 2; size <= SORTN; size <<= 1) {
        for (unsigned stride = size >> 1; stride > 0; stride >>= 1) {
            if (stride >= 32 || prev_stride >= 32) __syncthreads();
            else __syncwarp();
            #pragma unroll
            for (int rep = 0; rep < SORTN / 1024; rep++) {
                int t = tid + rep * 1024;
                int l = t ^ (int)stride;
                if (l > t) {
                    unsigned long long a = sh_sort[t], b = sh_sort[l];
                    bool asc = ((t & (int)size) == 0);
                    if ((a > b) == asc) { sh_sort[t] = b; sh_sort[l] = a; }
                }
            }
            prev_stride = stride;
        }
    }

    if (tid == 0) kept_sh = 0;
    __syncthreads();
    kept = 0;

    for (int base = 0; base < PRE; base += 64) {
        if (tid < 64) {
            int ci = base + tid;
            if (ci < PRE) {
                unsigned idx = (unsigned)(sh_sort[ci] & 0xFFFFFFFFull);
                float4 bx = props[idx];
                u.s.cbox[tid]  = bx;
                u.s.carea[tid] = areaf(bx);
                u.s.flags[tid] = 0;
            } else {
                u.s.cbox[tid]  = make_float4(0.f, 0.f, 0.f, 0.f);
                u.s.carea[tid] = 0.f;
                u.s.flags[tid] = 1;
            }
        }
        __syncthreads();

        for (int p = tid; p < 64 * kept; p += 1024) {
            int c = p & 63, ki = p >> 6;
            if (iou_gt(u.s.cbox[c], u.s.carea[c], u.s.kbox[ki], u.s.karea[ki]))
                u.s.flags[c] = 1;
        }
        __syncthreads();

        if (tid < 32) {
            const int l = tid;
            float4 b0 = u.s.cbox[l],      b1 = u.s.cbox[l + 32];
            float  a0 = u.s.carea[l],     a1 = u.s.carea[l + 32];
            unsigned f0 = __ballot_sync(0xffffffffu, u.s.flags[l] != 0);
            unsigned f1 = __ballot_sync(0xffffffffu, u.s.flags[l + 32] != 0);
            unsigned long long rem = ~(((unsigned long long)f1 << 32) | (unsigned long long)f0);
            int kl = kept;
            while (rem && kl < POST) {
                int c = __ffsll((long long)rem) - 1;
                rem &= rem - 1;
                float4 cc = u.s.cbox[c];
                float  ca = u.s.carea[c];
                if (l == 0) {
                    u.s.kbox[kl]  = cc;
                    u.s.karea[kl] = ca;
                    float* o = out + ((size_t)img * POST + kl) * 5;
                    o[1] = cc.x; o[2] = cc.y; o[3] = cc.z; o[4] = cc.w;
                }
                kl++;
                bool s0 = (l > c)        && iou_gt(cc, ca, b0, a0);
                bool s1 = ((l + 32) > c) && iou_gt(cc, ca, b1, a1);
                unsigned m0 = __ballot_sync(0xffffffffu, s0);
                unsigned m1 = __ballot_sync(0xffffffffu, s1);
                rem &= ~(((unsigned long long)m1 << 32) | (unsigned long long)m0);
            }
            if (l == 0) kept_sh = kl;
        }
        __syncthreads();
        kept = kept_sh;
        if (kept >= POST) break;
    }
}

// ---------------- launch ----------------
extern "C" void kernel_launch(void* const* d_in, const int* in_sizes, int n_in,
                              void* d_out, int out_size) {
    const float* scores  = (const float*)d_in[0];
    const float* deltas  = (const float*)d_in[1];
    const float* im_info = (const float*)d_in[2];
    const float* anchors = (const float*)d_in[3];
    float* out = (float*)d_out;

    dim3 dgrid((NN + 255) / 256, BB);
    decode_kernel<<<dgrid, 256>>>(scores, deltas, im_info, anchors, out);
    fused_kernel<<<BB, 1024>>>(out);
}

// round 17
// speedup vs baseline: 1.0993x; 1.0993x over previous
#include <cuda_runtime.h>
#include <cstdint>

#define BB 4
#define AA 9
#define HH 50
#define WW 76
#define HW (HH * WW)
#define NN (AA * HW)               // 34200 boxes per image
#define PRE 4000
#define POST 300
#define SORTN 4096                 // slow path sort size
#define FASTN 2048                 // fast path sort size
#define NMS_THR 0.7f
#define NBINS 2048
#define FB 64
#define CHUNK 1088                 // per-warp compaction chunk (34*32)

// ---------------- helpers ----------------
__device__ __forceinline__ float areaf(float4 b) {
    return __fmul_rn(__fsub_rn(b.z, b.x), __fsub_rn(b.w, b.y));
}

__device__ __forceinline__ unsigned score_key(float s) {
    unsigned bits = __float_as_uint(s);
    return (bits & 0x80000000u) ? ~bits : (bits | 0x80000000u);
}

// Decision-exact IoU > 0.7 with banded compare: FDIV only inside [0.67, 0.73] band.
__device__ __forceinline__ bool iou_gt(float4 a, float aA, float4 b, float aB) {
    float xx1 = fmaxf(a.x, b.x);
    float yy1 = fmaxf(a.y, b.y);
    float xx2 = fminf(a.z, b.z);
    float yy2 = fminf(a.w, b.w);
    float w = fmaxf(__fsub_rn(xx2, xx1), 0.0f);
    float h = fmaxf(__fsub_rn(yy2, yy1), 0.0f);
    float inter = __fmul_rn(w, h);
    float denom = __fadd_rn(__fsub_rn(__fadd_rn(aA, aB), inter), 1e-9f);
    if (inter < __fmul_rn(0.67f, denom)) return false;
    if (inter > __fmul_rn(0.73f, denom)) return true;
    return __fdiv_rn(inter, denom) > NMS_THR;
}

// Lazy box decode for candidate idx ( = p*AA + a ), identical arithmetic to the
// original decode kernel.
__device__ __forceinline__ float4 decode_box(int idx, int img,
                                             const float* __restrict__ deltas,
                                             const float* __restrict__ anchors,
                                             float hiw, float hih) {
    int a = idx % AA;
    int p = idx / AA;
    int x = p % WW;
    int y = p / WW;

    float sx = (float)(x * 16);
    float sy = (float)(y * 16);
    float ax1 = __fadd_rn(anchors[a * 4 + 0], sx);
    float ay1 = __fadd_rn(anchors[a * 4 + 1], sy);
    float ax2 = __fadd_rn(anchors[a * 4 + 2], sx);
    float ay2 = __fadd_rn(anchors[a * 4 + 3], sy);

    float w  = __fadd_rn(__fsub_rn(ax2, ax1), 1.0f);
    float h  = __fadd_rn(__fsub_rn(ay2, ay1), 1.0f);
    float cx = __fadd_rn(ax1, __fmul_rn(0.5f, w));
    float cy = __fadd_rn(ay1, __fmul_rn(0.5f, h));

    size_t dbase = ((size_t)img * 4 * AA + a * 4) * HW + p;
    float dx  = deltas[dbase];
    float dy  = deltas[dbase + HW];
    float dz  = deltas[dbase + 2 * HW];
    float dw_ = deltas[dbase + 3 * HW];

    float pcx = __fadd_rn(__fmul_rn(dx, w), cx);
    float pcy = __fadd_rn(__fmul_rn(dy, h), cy);
    float pw  = __fmul_rn(expf(dz),  w);
    float ph  = __fmul_rn(expf(dw_), h);

    float x1 = __fsub_rn(pcx, __fmul_rn(0.5f, pw));
    float y1 = __fsub_rn(pcy, __fmul_rn(0.5f, ph));
    float x2 = __fadd_rn(pcx, __fmul_rn(0.5f, pw));
    float y2 = __fadd_rn(pcy, __fmul_rn(0.5f, ph));

    x1 = fminf(fmaxf(x1, 0.0f), hiw);
    y1 = fminf(fmaxf(y1, 0.0f), hih);
    x2 = fminf(fmaxf(x2, 0.0f), hiw);
    y2 = fminf(fmaxf(y2, 0.0f), hih);
    return make_float4(x1, y1, x2, y2);
}

// score memory index j = a*HW + p  ->  candidate index idx = p*AA + a
__device__ __forceinline__ unsigned j_to_idx(int j) {
    int a = j / HW;
    int p = j - a * HW;
    return (unsigned)(p * AA + a);
}

// ---------------- shared-mem state ----------------
struct Batch {
    float4 cbox[FB];
    float  carea[FB];
    __align__(8) unsigned long long mat[FB];   // 64-bit suppression rows
    unsigned dead[2];
};
struct NmsFast {
    float4 kbox[POST];
    float  karea[POST];
    Batch  b[2];
};
struct NmsSlow {
    float4 kbox[POST];
    float  karea[POST];
    float4 cbox[64];
    float  carea[64];
    int    flags[64];
};
union SharedU {
    unsigned hist[NBINS];
    NmsFast  f;
    NmsSlow  s;
};

// ---------------- single fused kernel: everything per image ----------------
__global__ void __launch_bounds__(1024) fused_kernel(const float* __restrict__ scores,
                                                     const float* __restrict__ deltas,
                                                     const float* __restrict__ im_info,
                                                     const float* __restrict__ anchors,
                                                     float* __restrict__ out) {
    const int img = blockIdx.x;
    const float* simg = scores + (size_t)img * NN;
    const int tid = threadIdx.x;
    const int lane = tid & 31, wid = tid >> 5;

    __shared__ unsigned long long sh_sort[SORTN];
    __shared__ SharedU u;
    __shared__ unsigned csum[64];
    __shared__ unsigned warpsum[32];
    __shared__ unsigned cursor, sh_cnt, sh_T, sh_need, sh_bucket, eqbase, chunk_total;
    __shared__ int kept_sh, slow_sh;
    __shared__ float sh_hiw, sh_hih;

    // ---- output prefill [img, 0,0,0,0] (slow-path partial rows need it) ----
    {
        float* ob = out + (size_t)img * POST * 5;
        for (int r = tid; r < POST * 5; r += 1024)
            ob[r] = ((r % 5) == 0) ? (float)img : 0.0f;
    }
    if (tid == 0) {
        sh_hiw = __fsub_rn(im_info[img * 3 + 1], 1.0f);
        sh_hih = __fsub_rn(im_info[img * 3 + 0], 1.0f);
    }

    // ---- in-block histogram of score keys (top 11 bits) ----
    #pragma unroll
    for (int rep = 0; rep < NBINS / 1024; rep++)
        u.hist[tid + rep * 1024] = 0;
    __syncthreads();
    for (int j = tid; j < NN; j += 1024)
        atomicAdd(&u.hist[score_key(simg[j]) >> 21], 1u);
    __syncthreads();
    if (tid < 64) {
        unsigned s = 0;
        #pragma unroll
        for (int v = 0; v < 32; v++) s += u.hist[tid * 32 + v];
        csum[tid] = s;
    }
    __syncthreads();
    if (tid == 0) {
        unsigned cum = 0;
        int ch = 63;
        for (; ch > 0; ch--) {
            if (cum + csum[ch] >= 1024u) break;
            cum += csum[ch];
        }
        int bsel = ch * 32;
        for (int v = ch * 32 + 31; v >= ch * 32; v--) {
            if (cum + u.hist[v] >= 1024u) { bsel = v; break; }
            cum += u.hist[v];
        }
        sh_T = (unsigned)bsel << 21;
        sh_cnt = cum + u.hist[bsel];
        cursor = 0;
        kept_sh = 0;
        slow_sh = 0;
    }
    __syncthreads();
    const unsigned T = sh_T;
    const int cnt = (int)sh_cnt;          // >= 1024 always
    const bool fastok = (cnt <= FASTN);
    const float hiw = sh_hiw, hih = sh_hih;

    if (fastok) {
        // ---- atomic-free two-pass compaction (scores L1-hot; warp-uniform loops) ----
        sh_sort[tid] = 0xFFFFFFFFFFFFFFFFull;
        sh_sort[tid + 1024] = 0xFFFFFFFFFFFFFFFFull;

        const int lo = wid * CHUNK;
        const int hi = min(lo + CHUNK, NN);
        const int iters = (hi - lo + 31) >> 5;

        unsigned mycnt = 0;
        for (int it = 0; it < iters; it++) {
            int j = lo + it * 32 + lane;
            bool take = (j < hi) && (score_key(simg[j]) >= T);
            unsigned m = __ballot_sync(0xffffffffu, take);
            mycnt += (unsigned)__popc(m);
        }
        if (lane == 0) warpsum[wid] = mycnt;
        __syncthreads();
        if (wid == 0) {
            unsigned wv = warpsum[lane];
            unsigned vv = wv;
            #pragma unroll
            for (int off = 1; off < 32; off <<= 1) {
                unsigned tmp = __shfl_up_sync(0xffffffffu, vv, off);
                if (lane >= off) vv += tmp;
            }
            warpsum[lane] = vv - wv;
        }
        __syncthreads();
        unsigned basew = warpsum[wid];
        for (int it = 0; it < iters; it++) {
            int j = lo + it * 32 + lane;
            unsigned k = (j < hi) ? score_key(simg[j]) : 0u;
            bool take = (j < hi) && (k >= T);
            unsigned m = __ballot_sync(0xffffffffu, take);
            if (take) {
                unsigned pos = basew + (unsigned)__popc(m & ((1u << lane) - 1u));
                sh_sort[pos] = (((unsigned long long)(~k)) << 32) | j_to_idx(j);
            }
            basew += (unsigned)__popc(m);
        }
        __syncthreads();

        // ---- bitonic sort ascending on (~key, idx): key desc, idx asc ----
        unsigned prev_stride = 0xFFFFu;
        for (unsigned size = 2; size <= FASTN; size <<= 1) {
            for (unsigned stride = size >> 1; stride > 0; stride >>= 1) {
                if (stride >= 32 || prev_stride >= 32) __syncthreads();
                else __syncwarp();
                #pragma unroll
                for (int rep = 0; rep < FASTN / 1024; rep++) {
                    int t = tid + rep * 1024;
                    int l = t ^ (int)stride;
                    if (l > t) {
                        unsigned long long a = sh_sort[t], b = sh_sort[l];
                        bool asc = ((t & (int)size) == 0);
                        if ((a > b) == asc) { sh_sort[t] = b; sh_sort[l] = a; }
                    }
                }
                prev_stride = stride;
            }
        }
        __syncthreads();

        // ---- pipelined batch-64 NMS (lazy box decode at gather) ----
        if (tid < FB) {
            unsigned idx = (unsigned)(sh_sort[tid] & 0xFFFFFFFFull);
            float4 bx = decode_box((int)idx, img, deltas, anchors, hiw, hih);
            u.f.b[0].cbox[tid]  = bx;
            u.f.b[0].carea[tid] = areaf(bx);
        }
        if (tid < 2) u.f.b[0].dead[tid] = 0u;
        __syncthreads();
        for (int t = wid; t < 128; t += 32) {
            int r = t >> 1, hw2 = t & 1;
            int c = hw2 * 32 + lane;
            bool s = (c > r) &&
                     iou_gt(u.f.b[0].cbox[r], u.f.b[0].carea[r],
                            u.f.b[0].cbox[c], u.f.b[0].carea[c]);
            unsigned m = __ballot_sync(0xffffffffu, s);
            if (lane == 0) ((unsigned*)&u.f.b[0].mat[r])[hw2] = m;
        }
        __syncthreads();

        int kept = 0, prev = 0;
        for (int bi = 0; ; bi++) {
            const int base = bi * FB;
            const int cur = bi & 1, nxt = cur ^ 1;

            // region A: delta phase-1 (cur vs keeps [prev,kept))
            if (kept > prev) {
                int c = tid & 63;
                int kb = tid >> 6;                      // 0..15 slices
                float4 cb = u.f.b[cur].cbox[c];
                float  ca = u.f.b[cur].carea[c];
                for (int k = prev + kb; k < kept; k += 16) {
                    if (iou_gt(cb, ca, u.f.kbox[k], u.f.karea[k])) {
                        atomicOr(&u.f.b[cur].dead[c >> 5], 1u << (c & 31));
                        break;
                    }
                }
            }
            if (tid < 2) {
                int plo = (base + FB) + tid * 32;
                unsigned pad;
                if (plo >= cnt)            pad = 0xFFFFFFFFu;
                else if (plo + 32 <= cnt)  pad = 0u;
                else                       pad = ~((1u << (cnt - plo)) - 1u);
                u.f.b[nxt].dead[tid] = pad;
            }
            __syncthreads();

            // region B: thread 0 = phase-2(cur); warps 1..31 = prep(nxt)
            if (tid == 0) {
                unsigned long long rem =
                    ~(((unsigned long long)u.f.b[cur].dead[1] << 32) |
                       (unsigned long long)u.f.b[cur].dead[0]);
                int kl = kept;
                while (rem && kl < POST) {
                    int c = __ffsll((long long)rem) - 1;
                    float4 cc = u.f.b[cur].cbox[c];
                    u.f.kbox[kl]  = cc;
                    u.f.karea[kl] = u.f.b[cur].carea[c];
                    kl++;
                    rem &= ~u.f.b[cur].mat[c];
                    rem &= ~(1ull << c);
                }
                kept_sh = kl;
            } else if (tid >= 32) {
                const int pt = tid - 32;
                const int nb = base + FB;
                if (pt < FB) {
                    int ci = nb + pt;
                    if (ci < cnt) {
                        unsigned idx = (unsigned)(sh_sort[ci] & 0xFFFFFFFFull);
                        float4 bx = decode_box((int)idx, img, deltas, anchors, hiw, hih);
                        u.f.b[nxt].cbox[pt]  = bx;
                        u.f.b[nxt].carea[pt] = areaf(bx);
                    } else {
                        u.f.b[nxt].cbox[pt]  = make_float4(0.f, 0.f, 0.f, 0.f);
                        u.f.b[nxt].carea[pt] = 0.f;
                    }
                }
                asm volatile("bar.sync 1, 992;" ::: "memory");
                for (int t = wid - 1; t < 128; t += 31) {
                    int r = t >> 1, hw2 = t & 1;
                    int c = hw2 * 32 + lane;
                    bool s = (c > r) &&
                             iou_gt(u.f.b[nxt].cbox[r], u.f.b[nxt].carea[r],
                                    u.f.b[nxt].cbox[c], u.f.b[nxt].carea[c]);
                    unsigned m = __ballot_sync(0xffffffffu, s);
                    if (lane == 0) ((unsigned*)&u.f.b[nxt].mat[r])[hw2] = m;
                }
                int q = tid - 32;
                if (q < 960 && kept > 0) {
                    int c = q & 63;
                    int kb = q >> 6;                    // 0..14
                    unsigned cbit = 1u << (c & 31);
                    float4 cb = u.f.b[nxt].cbox[c];
                    float  ca = u.f.b[nxt].carea[c];
                    for (int k = kb; k < kept; k += 15) {
                        if (u.f.b[nxt].dead[c >> 5] & cbit) break;
                        if (iou_gt(cb, ca, u.f.kbox[k], u.f.karea[k])) {
                            atomicOr(&u.f.b[nxt].dead[c >> 5], cbit);
                            break;
                        }
                    }
                }
            }
            __syncthreads();
            prev = kept;
            kept = kept_sh;
            if (kept >= POST) break;
            if (base + FB >= cnt) break;
        }
        if (tid == 0) slow_sh = (kept < POST) ? 1 : 0;
        __syncthreads();
        if (!slow_sh) {
            if (tid < POST) {
                float4 cc = u.f.kbox[tid];
                float* o = out + ((size_t)img * POST + tid) * 5;
                o[0] = (float)img;
                o[1] = cc.x; o[2] = cc.y; o[3] = cc.z; o[4] = cc.w;
            }
            return;
        }
    }

    // ================= SLOW fallback (exact top-4000 pipeline) =================
    if (tid == 0) sh_need = PRE;
    __syncthreads();

    unsigned prefix = 0, pmask = 0;
    const int shifts[3]  = {21, 10, 0};
    const int nbins3[3]  = {2048, 2048, 1024};
    for (int r = 0; r < 3; r++) {
        const int shift = shifts[r];
        const unsigned bmask = (unsigned)nbins3[r] - 1u;
        for (int i = tid; i < 2048; i += 1024) u.hist[i] = 0;
        __syncthreads();
        for (int j = tid; j < NN; j += 1024) {
            unsigned k = score_key(simg[j]);
            if ((k & pmask) == prefix) atomicAdd(&u.hist[(k >> shift) & bmask], 1u);
        }
        __syncthreads();
        const int nch = nbins3[r] >> 5;
        if (tid < nch) {
            unsigned s = 0;
            for (int v = 0; v < 32; v++) s += u.hist[tid * 32 + v];
            csum[tid] = s;
        }
        __syncthreads();
        if (tid == 0) {
            unsigned nd = sh_need, cum = 0;
            int ch = nch - 1;
            for (; ch > 0; ch--) {
                if (cum + csum[ch] >= nd) break;
                cum += csum[ch];
            }
            int bsel = ch * 32;
            for (int v = ch * 32 + 31; v >= ch * 32; v--) {
                if (cum + u.hist[v] >= nd) { bsel = v; break; }
                cum += u.hist[v];
            }
            sh_bucket = (unsigned)bsel;
            sh_need = nd - cum;
        }
        __syncthreads();
        prefix |= (sh_bucket << shift);
        pmask  |= (bmask << shift);
        __syncthreads();
    }
    const unsigned Ts = prefix;
    const unsigned need_eq = sh_need;

    if (tid == 0) { cursor = 0; eqbase = 0; }
    for (int i = tid; i < SORTN; i += 1024)
        sh_sort[i] = 0xFFFFFFFFFFFFFFFFull;
    __syncthreads();

    // ordered compaction over score order j; idx = j_to_idx(j).
    // NOTE: reference tie order is by candidate idx asc. Keys equal to Ts must be
    // taken as the FIRST need_eq in idx order. j order != idx order, so ordered
    // compaction must scan in idx order: iterate idx directly, score at
    // j = a*HW + p  where a = idx%AA, p = idx/AA.
    for (int base = 0; base < NN; base += 1024) {
        int idx = base + tid;
        unsigned k = 0u;
        if (idx < NN) {
            int a = idx % AA;
            int p = idx / AA;
            k = score_key(simg[a * HW + p]);
        }
        unsigned isgt = (idx < NN && k > Ts) ? 1u : 0u;
        unsigned iseq = (idx < NN && k == Ts) ? 1u : 0u;

        unsigned v = iseq;
        #pragma unroll
        for (int off = 1; off < 32; off <<= 1) {
            unsigned tmp = __shfl_up_sync(0xffffffffu, v, off);
            if (lane >= off) v += tmp;
        }
        if (lane == 31) warpsum[wid] = v;
        __syncthreads();
        if (wid == 0) {
            unsigned wv = warpsum[lane];
            unsigned vv = wv;
            #pragma unroll
            for (int off = 1; off < 32; off <<= 1) {
                unsigned tmp = __shfl_up_sync(0xffffffffu, vv, off);
                if (lane >= off) vv += tmp;
            }
            warpsum[lane] = vv - wv;
            if (lane == 31) chunk_total = vv;
        }
        __syncthreads();
        unsigned excl = v - iseq + warpsum[wid];
        unsigned eqrank = eqbase + excl;
        bool take = isgt || (iseq && eqrank < need_eq);
        if (take) {
            unsigned pos = atomicAdd(&cursor, 1u);
            sh_sort[pos] = (((unsigned long long)(~k)) << 32) | (unsigned)idx;
        }
        __syncthreads();
        if (tid == 0) eqbase += chunk_total;
        __syncthreads();
    }

    unsigned prev_stride = 0xFFFFu;
    for (unsigned size = 2; size <= SORTN; size <<= 1) {
        for (unsigned stride = size >> 1; stride > 0; stride >>= 1) {
            if (stride >= 32 || prev_stride >= 32) __syncthreads();
            else __syncwarp();
            #pragma unroll
            for (int rep = 0; rep < SORTN / 1024; rep++) {
                int t = tid + rep * 1024;
                int l = t ^ (int)stride;
                if (l > t) {
                    unsigned long long a = sh_sort[t], b = sh_sort[l];
                    bool asc = ((t & (int)size) == 0);
                    if ((a > b) == asc) { sh_sort[t] = b; sh_sort[l] = a; }
                }
            }
            prev_stride = stride;
        }
    }

    if (tid == 0) kept_sh = 0;
    __syncthreads();
    int kept = 0;

    for (int base = 0; base < PRE; base += 64) {
        if (tid < 64) {
            int ci = base + tid;
            if (ci < PRE) {
                unsigned idx = (unsigned)(sh_sort[ci] & 0xFFFFFFFFull);
                float4 bx = decode_box((int)idx, img, deltas, anchors, hiw, hih);
                u.s.cbox[tid]  = bx;
                u.s.carea[tid] = areaf(bx);
                u.s.flags[tid] = 0;
            } else {
                u.s.cbox[tid]  = make_float4(0.f, 0.f, 0.f, 0.f);
                u.s.carea[tid] = 0.f;
                u.s.flags[tid] = 1;
            }
        }
        __syncthreads();

        for (int p = tid; p < 64 * kept; p += 1024) {
            int c = p & 63, ki = p >> 6;
            if (iou_gt(u.s.cbox[c], u.s.carea[c], u.s.kbox[ki], u.s.karea[ki]))
                u.s.flags[c] = 1;
        }
        __syncthreads();

        if (tid < 32) {
            const int l = tid;
            float4 b0 = u.s.cbox[l],      b1 = u.s.cbox[l + 32];
            float  a0 = u.s.carea[l],     a1 = u.s.carea[l + 32];
            unsigned f0 = __ballot_sync(0xffffffffu, u.s.flags[l] != 0);
            unsigned f1 = __ballot_sync(0xffffffffu, u.s.flags[l + 32] != 0);
            unsigned long long rem = ~(((unsigned long long)f1 << 32) | (unsigned long long)f0);
            int kl = kept;
            while (rem && kl < POST) {
                int c = __ffsll((long long)rem) - 1;
                rem &= rem - 1;
                float4 cc = u.s.cbox[c];
                float  ca = u.s.carea[c];
                if (l == 0) {
                    u.s.kbox[kl]  = cc;
                    u.s.karea[kl] = ca;
                    float* o = out + ((size_t)img * POST + kl) * 5;
                    o[1] = cc.x; o[2] = cc.y; o[3] = cc.z; o[4] = cc.w;
                }
                kl++;
                bool s0 = (l > c)        && iou_gt(cc, ca, b0, a0);
                bool s1 = ((l + 32) > c) && iou_gt(cc, ca, b1, a1);
                unsigned m0 = __ballot_sync(0xffffffffu, s0);
                unsigned m1 = __ballot_sync(0xffffffffu, s1);
                rem &= ~(((unsigned long long)m1 << 32) | (unsigned long long)m0);
            }
            if (l == 0) kept_sh = kl;
        }
        __syncthreads();
        kept = kept_sh;
        if (kept >= POST) break;
    }
}

// ---------------- launch ----------------
extern "C" void kernel_launch(void* const* d_in, const int* in_sizes, int n_in,
                              void* d_out, int out_size) {
    const float* scores  = (const float*)d_in[0];
    const float* deltas  = (const float*)d_in[1];
    const float* im_info = (const float*)d_in[2];
    const float* anchors = (const float*)d_in[3];
    float* out = (float*)d_out;

    fused_kernel<<<BB, 1024>>>(scores, deltas, im_info, anchors, out);
}